// round 8
// baseline (speedup 1.0000x reference)
#include <cuda_runtime.h>

// Problem constants: B=4, C=64, N=512, H=128, 2C=128.
#define B_ 4
#define C_ 64
#define N_ 512
#define H_ 128

typedef unsigned long long u64;

// Scratch (h-major, plain f32):
//   g_A [b][h][n] = b1[h] + sum_c x[b,c,n]*W1[c][h]
//   g_Bv[b][h][n] =         sum_c x[b,c,n]*W1[C+c][h]
//   g_PQp[gy][b][n]: gy 0..3 = P partials (32-h chunks, b2 folded into gy 0),
//                    gy 4..7 = Q partials; P = sum_h (W2[h]/2)*A, Q likewise for Bv.
__device__ float g_A  [B_ * H_ * N_];
__device__ float g_Bv [B_ * H_ * N_];
__device__ float g_PQp[8 * B_ * N_];

// 32(i) x 64(j) tiles. Compute tiles (contain some j>i): It <= 2*Jt+1, 72/batch.
// Zero tiles (It >= 2*Jt+2): 56/batch.
__constant__ signed char c_IT[72] = {
    0,1,
    0,1,2,3,
    0,1,2,3,4,5,
    0,1,2,3,4,5,6,7,
    0,1,2,3,4,5,6,7,8,9,
    0,1,2,3,4,5,6,7,8,9,10,11,
    0,1,2,3,4,5,6,7,8,9,10,11,12,13,
    0,1,2,3,4,5,6,7,8,9,10,11,12,13,14,15
};
__constant__ signed char c_JT[72] = {
    0,0, 1,1,1,1, 2,2,2,2,2,2, 3,3,3,3,3,3,3,3,
    4,4,4,4,4,4,4,4,4,4, 5,5,5,5,5,5,5,5,5,5,5,5,
    6,6,6,6,6,6,6,6,6,6,6,6,6,6, 7,7,7,7,7,7,7,7,7,7,7,7,7,7,7,7
};
__constant__ signed char c_ZI[56] = {
    2,3,4,5,6,7,8,9,10,11,12,13,14,15,
    4,5,6,7,8,9,10,11,12,13,14,15,
    6,7,8,9,10,11,12,13,14,15,
    8,9,10,11,12,13,14,15,
    10,11,12,13,14,15,
    12,13,14,15,
    14,15
};
__constant__ signed char c_ZJ[56] = {
    0,0,0,0,0,0,0,0,0,0,0,0,0,0,
    1,1,1,1,1,1,1,1,1,1,1,1,
    2,2,2,2,2,2,2,2,2,2,
    3,3,3,3,3,3,3,3,
    4,4,4,4,4,4,
    5,5,5,5,
    6,6
};

// ---- packed f32x2 helpers (kernel 1 only) ----------------------------------
__device__ __forceinline__ u64 f32x2_fma(u64 a, u64 b, u64 c) {
    u64 r; asm("fma.rn.f32x2 %0, %1, %2, %3;" : "=l"(r) : "l"(a), "l"(b), "l"(c)); return r;
}
__device__ __forceinline__ u64 dup32(float x) {
    u64 r; asm("mov.b64 %0, {%1, %1};" : "=l"(r) : "f"(x)); return r;
}
__device__ __forceinline__ float lo32(u64 v) { return __uint_as_float((unsigned)v); }
__device__ __forceinline__ float hi32(u64 v) { return __uint_as_float((unsigned)(v >> 32)); }

// ---------------------------------------------------------------------------
// Kernel 1: shared-staged GEMM  x^T @ [W1a | W1b] -> g_A (b1 folded), g_Bv,
// P/Q partials into g_PQp (b2 folded into gy==0).
// grid (N/128=4, 8 hu-chunks of 32, B), block 256. Thread: 2 n x 8 hu (f32x2).
// ---------------------------------------------------------------------------
__global__ void __launch_bounds__(256) precompute_AB(
        const float* __restrict__ x,
        const float* __restrict__ W1,
        const float* __restrict__ b1,
        const float* __restrict__ W2,
        const float* __restrict__ b2) {
    __shared__ float xs[C_ * 128];     // [c][n_loc]  32 KB
    __shared__ float ws[C_ * 32];      // [c][k]       8 KB
    __shared__ float w2s[32];
    __shared__ float b1s[32];
    __shared__ float sPart[4 * 128];   // [hgroup][n_loc] 2 KB

    const int tid = threadIdx.x;
    const int n0  = blockIdx.x * 128;
    const int gy  = blockIdx.y;        // 0..7
    const int b   = blockIdx.z;
    const bool isA = (gy < 4);
    const int h0   = (isA ? gy : gy - 4) * 32;   // output h base 0..96
    const int crow = isA ? 0 : C_;               // W1 row offset

    // Stage x tile: 64c x 128n = 2048 float4, 8 per thread.
    const float* xb = x + (size_t)(b * C_) * N_ + n0;
    #pragma unroll
    for (int r = 0; r < 8; r++) {
        int idx = tid + 256 * r;
        int c   = idx >> 5;
        int n4  = idx & 31;
        ((float4*)(xs + c * 128))[n4] = ((const float4*)(xb + (size_t)c * N_))[n4];
    }
    // Stage W slice: 64c x 32hu = 512 float4, 2 per thread.
    #pragma unroll
    for (int r = 0; r < 2; r++) {
        int idx = tid + 256 * r;
        int c   = idx >> 3;
        int k4  = idx & 7;
        ((float4*)(ws + c * 32))[k4] =
            ((const float4*)(W1 + (size_t)(crow + c) * H_ + h0))[k4];
    }
    if (tid < 32) {
        w2s[tid] = 0.5f * W2[h0 + tid];
        b1s[tid] = isA ? b1[h0 + tid] : 0.0f;
    }
    __syncthreads();

    const int nl0 = (tid & 63) * 2;
    const int hl0 = (tid >> 6) * 8;

    u64 acc[2][4];
    #pragma unroll
    for (int p = 0; p < 2; p++)
        #pragma unroll
        for (int k = 0; k < 4; k++) acc[p][k] = 0ULL;

    #pragma unroll 8
    for (int c = 0; c < C_; c++) {
        float2 xv = *(const float2*)(xs + c * 128 + nl0);
        u64 x0 = dup32(xv.x);
        u64 x1 = dup32(xv.y);
        const ulonglong2* wp = (const ulonglong2*)(ws + c * 32 + hl0);
        ulonglong2 w01 = wp[0];
        ulonglong2 w23 = wp[1];
        acc[0][0] = f32x2_fma(x0, w01.x, acc[0][0]);
        acc[0][1] = f32x2_fma(x0, w01.y, acc[0][1]);
        acc[0][2] = f32x2_fma(x0, w23.x, acc[0][2]);
        acc[0][3] = f32x2_fma(x0, w23.y, acc[0][3]);
        acc[1][0] = f32x2_fma(x1, w01.x, acc[1][0]);
        acc[1][1] = f32x2_fma(x1, w01.y, acc[1][1]);
        acc[1][2] = f32x2_fma(x1, w23.x, acc[1][2]);
        acc[1][3] = f32x2_fma(x1, w23.y, acc[1][3]);
    }

    // Epilogue: add b1, store float2 (n, n+1) per h, accumulate P/Q partials.
    float* outb = (isA ? g_A : g_Bv) + (size_t)(b * H_ + h0) * N_ + n0 + nl0;
    float p0 = 0.f, p1 = 0.f;
    #pragma unroll
    for (int k = 0; k < 4; k++) {
        #pragma unroll
        for (int s = 0; s < 2; s++) {
            int hl = hl0 + 2 * k + s;
            float bias = b1s[hl];
            float a0 = (s ? hi32(acc[0][k]) : lo32(acc[0][k])) + bias;
            float a1 = (s ? hi32(acc[1][k]) : lo32(acc[1][k])) + bias;
            *(float2*)(outb + (size_t)hl * N_) = make_float2(a0, a1);
            float w = w2s[hl];
            p0 = fmaf(w, a0, p0);
            p1 = fmaf(w, a1, p1);
        }
    }
    sPart[(tid >> 6) * 128 + nl0]     = p0;
    sPart[(tid >> 6) * 128 + nl0 + 1] = p1;
    __syncthreads();
    if (tid < 128) {
        float s = sPart[tid] + sPart[128 + tid] + sPart[256 + tid] + sPart[384 + tid];
        if (gy == 0) s += b2[0];
        g_PQp[gy * (B_ * N_) + b * N_ + n0 + tid] = s;
    }
}

// ---------------------------------------------------------------------------
// Kernel 2: grid 512 (1D), 256 threads.
//   bid < 288: compute 32x64 tile t=bid>>2, b=bid&3:
//     y[i,j] = P_i + Q_j + sum_h w'_h |A_ih + B_jh|   (relu(u) = (u+|u|)/2)
//   bid >= 288: zero-fill below-diagonal 32x64 tiles.
// Thread: 2i x 4j scalar; full 128-hh panel staged once (48 KB smem);
// abs folds into the FFMA |src| modifier (no alu work in the inner loop).
// ---------------------------------------------------------------------------
__global__ void __launch_bounds__(256) pairwise_score(
        const float* __restrict__ W2,
        float* __restrict__ out) {
    const int t   = blockIdx.x;
    const int tid = threadIdx.x;

    if (t >= 288) {   // zero-fill tiles
        int z  = t - 288;
        int b  = z & 3;
        int zt = z >> 2;              // 0..55
        float* outb = out + (size_t)b * N_ * N_
                    + (size_t)(c_ZI[zt] * 32) * N_ + c_ZJ[zt] * 64;
        const float4 zf = make_float4(0.f, 0.f, 0.f, 0.f);
        #pragma unroll
        for (int r = 0; r < 2; r++) {
            int l  = tid + 256 * r;   // float4 index 0..511
            int ii = l >> 4;
            int j4 = l & 15;
            ((float4*)(outb + (size_t)ii * N_))[j4] = zf;
        }
        return;
    }

    const int b  = t & 3;
    const int tl = t >> 2;            // 0..71
    const int It = c_IT[tl];
    const int Jt = c_JT[tl];
    float* outb = out + (size_t)b * N_ * N_;

    __shared__ float Ash[H_ * 32];    // [hh][ii] 16 KB (all 128 hh)
    __shared__ float Bsh[H_ * 64];    // [hh][jj] 32 KB (all 128 hh)
    __shared__ float Wsh[H_];         // w/2
    __shared__ float Psh[32];         // includes b2
    __shared__ float Qsh[64];

    // Stage the full panel once.
    const float* Ag = g_A  + (size_t)(b * H_) * N_ + It * 32;
    const float* Bg = g_Bv + (size_t)(b * H_) * N_ + Jt * 64;
    #pragma unroll
    for (int r = 0; r < 4; r++) {     // A: 128hh x 8 float4 = 1024
        int l  = tid + 256 * r;
        int hh = l >> 3;
        int c4 = l & 7;
        ((float4*)(Ash + hh * 32))[c4] = ((const float4*)(Ag + (size_t)hh * N_))[c4];
    }
    #pragma unroll
    for (int r = 0; r < 8; r++) {     // B: 128hh x 16 float4 = 2048
        int l  = tid + 256 * r;
        int hh = l >> 4;
        int c4 = l & 15;
        ((float4*)(Bsh + hh * 64))[c4] = ((const float4*)(Bg + (size_t)hh * N_))[c4];
    }
    if (tid < H_) {
        Wsh[tid] = 0.5f * W2[tid];
    } else if (tid < 160) {
        int k = tid - 128;            // 0..31
        int n = It * 32 + k;
        Psh[k] = g_PQp[0 * B_ * N_ + b * N_ + n] + g_PQp[1 * B_ * N_ + b * N_ + n]
               + g_PQp[2 * B_ * N_ + b * N_ + n] + g_PQp[3 * B_ * N_ + b * N_ + n];
    } else if (tid < 224) {
        int k = tid - 160;            // 0..63
        int n = Jt * 64 + k;
        Qsh[k] = g_PQp[4 * B_ * N_ + b * N_ + n] + g_PQp[5 * B_ * N_ + b * N_ + n]
               + g_PQp[6 * B_ * N_ + b * N_ + n] + g_PQp[7 * B_ * N_ + b * N_ + n];
    }
    __syncthreads();

    const int il0 = (tid >> 4) * 2;   // 0..30
    const int jl0 = (tid & 15) * 4;   // 0..60

    float acc[2][4];
    #pragma unroll
    for (int p = 0; p < 2; p++)
        #pragma unroll
        for (int q = 0; q < 4; q++) acc[p][q] = 0.0f;

    const float* Ap = Ash + il0;
    const float* Bp = Bsh + jl0;
    #pragma unroll 8
    for (int hh = 0; hh < H_; hh++) {
        float  w  = Wsh[hh];
        float2 a  = *(const float2*)(Ap + hh * 32);
        float4 bv = *(const float4*)(Bp + hh * 64);
        acc[0][0] = fmaf(fabsf(a.x + bv.x), w, acc[0][0]);
        acc[0][1] = fmaf(fabsf(a.x + bv.y), w, acc[0][1]);
        acc[0][2] = fmaf(fabsf(a.x + bv.z), w, acc[0][2]);
        acc[0][3] = fmaf(fabsf(a.x + bv.w), w, acc[0][3]);
        acc[1][0] = fmaf(fabsf(a.y + bv.x), w, acc[1][0]);
        acc[1][1] = fmaf(fabsf(a.y + bv.y), w, acc[1][1]);
        acc[1][2] = fmaf(fabsf(a.y + bv.z), w, acc[1][2]);
        acc[1][3] = fmaf(fabsf(a.y + bv.w), w, acc[1][3]);
    }

    const int i0 = It * 32 + il0;
    const int j0 = Jt * 64 + jl0;
    const bool needMask = (It >= 2 * Jt);   // tile touches/straddles the diagonal

    float p0 = Psh[il0], p1 = Psh[il0 + 1];
    float q0 = Qsh[jl0], q1 = Qsh[jl0 + 1], q2 = Qsh[jl0 + 2], q3 = Qsh[jl0 + 3];

    float4 v0, v1;
    v0.x = p0 + q0 + acc[0][0]; v0.y = p0 + q1 + acc[0][1];
    v0.z = p0 + q2 + acc[0][2]; v0.w = p0 + q3 + acc[0][3];
    v1.x = p1 + q0 + acc[1][0]; v1.y = p1 + q1 + acc[1][1];
    v1.z = p1 + q2 + acc[1][2]; v1.w = p1 + q3 + acc[1][3];

    if (needMask) {   // strict upper-triangle mask j > i
        if (!(j0 + 0 > i0)) v0.x = 0.f;
        if (!(j0 + 1 > i0)) v0.y = 0.f;
        if (!(j0 + 2 > i0)) v0.z = 0.f;
        if (!(j0 + 3 > i0)) v0.w = 0.f;
        int i1 = i0 + 1;
        if (!(j0 + 0 > i1)) v1.x = 0.f;
        if (!(j0 + 1 > i1)) v1.y = 0.f;
        if (!(j0 + 2 > i1)) v1.z = 0.f;
        if (!(j0 + 3 > i1)) v1.w = 0.f;
    }
    *(float4*)(outb + (size_t)i0 * N_ + j0)       = v0;
    *(float4*)(outb + (size_t)(i0 + 1) * N_ + j0) = v1;
}

// ---------------------------------------------------------------------------
// Inputs: 0:x (B,C,N) f32, 1:W1 (2C,H) f32, 2:b1 (H) f32, 3:W2 (H,1) f32,
//         4:b2 (1) f32.  Output: (B,N,N) f32.
// ---------------------------------------------------------------------------
extern "C" void kernel_launch(void* const* d_in, const int* in_sizes, int n_in,
                              void* d_out, int out_size) {
    const float* x  = (const float*)d_in[0];
    const float* W1 = (const float*)d_in[1];
    const float* b1 = (const float*)d_in[2];
    const float* W2 = (const float*)d_in[3];
    const float* b2 = (const float*)d_in[4];
    float* out = (float*)d_out;

    dim3 g1(N_ / 128, 8, B_);     // (4, 8, 4) = 128 blocks
    precompute_AB<<<g1, 256>>>(x, W1, b1, W2, b2);

    pairwise_score<<<512, 256>>>(W2, out);   // 288 compute + 224 zero-fill
}

// round 11
// speedup vs baseline: 1.1287x; 1.1287x over previous
#include <cuda_runtime.h>

// Problem constants: B=4, C=64, N=512, H=128, 2C=128.
#define B_ 4
#define C_ 64
#define N_ 512
#define H_ 128

typedef unsigned long long u64;

// Scratch (h-major, plain f32), PRESCALED by w_h/2 (signed):
//   g_A [b][h][n] = (W2[h]/2) * (b1[h] + sum_c x[b,c,n]*W1[c][h])
//   g_Bv[b][h][n] = (W2[h]/2) * (       sum_c x[b,c,n]*W1[C+c][h])
//   g_PQp[gy][b][n]: gy 0..3 = P partials (sum of g_A over 32-h chunks; b2 in gy0),
//                    gy 4..7 = Q partials (sum of g_Bv).
// Then y_ij = (P_i + Q_j) + sum_h sign(w_h) * |g_A[i,h] + g_Bv[j,h]|.
__device__ float g_A  [B_ * H_ * N_];
__device__ float g_Bv [B_ * H_ * N_];
__device__ float g_PQp[8 * B_ * N_];

// Upper-triangle (It<=Jt, 36) and strict-lower (It>Jt, 28) 64x64 tile lists.
__constant__ signed char c_IT[36] = {0,0,0,0,0,0,0,0, 1,1,1,1,1,1,1, 2,2,2,2,2,2,
                                     3,3,3,3,3, 4,4,4,4, 5,5,5, 6,6, 7};
__constant__ signed char c_JT[36] = {0,1,2,3,4,5,6,7, 1,2,3,4,5,6,7, 2,3,4,5,6,7,
                                     3,4,5,6,7, 4,5,6,7, 5,6,7, 6,7, 7};
__constant__ signed char c_LI[28] = {1, 2,2, 3,3,3, 4,4,4,4, 5,5,5,5,5,
                                     6,6,6,6,6,6, 7,7,7,7,7,7,7};
__constant__ signed char c_LJ[28] = {0, 0,1, 0,1,2, 0,1,2,3, 0,1,2,3,4,
                                     0,1,2,3,4,5, 0,1,2,3,4,5,6};

// ---- packed f32x2 helpers (sm_100+) ----------------------------------------
__device__ __forceinline__ u64 f32x2_add(u64 a, u64 b) {
    u64 r; asm("add.rn.f32x2 %0, %1, %2;" : "=l"(r) : "l"(a), "l"(b)); return r;
}
__device__ __forceinline__ u64 f32x2_fma(u64 a, u64 b, u64 c) {
    u64 r; asm("fma.rn.f32x2 %0, %1, %2, %3;" : "=l"(r) : "l"(a), "l"(b), "l"(c)); return r;
}
__device__ __forceinline__ u64 dup32(float x) {
    u64 r; asm("mov.b64 %0, {%1, %1};" : "=l"(r) : "f"(x)); return r;
}
__device__ __forceinline__ float lo32(u64 v) { return __uint_as_float((unsigned)v); }
__device__ __forceinline__ float hi32(u64 v) { return __uint_as_float((unsigned)(v >> 32)); }

// (t & 0x7fffffff) ^ s per 32-bit word: one LOP3 each (LUT (a&b)^c = 0x6A).
// Gives sign(w)*|t| for each packed lane when s = signbit(w).
__device__ __forceinline__ u64 absxor2(u64 t, unsigned s) {
    unsigned tl, th, rl, rh;
    asm("mov.b64 {%0,%1}, %2;" : "=r"(tl), "=r"(th) : "l"(t));
    asm("lop3.b32 %0, %1, 0x7fffffff, %2, 0x6A;" : "=r"(rl) : "r"(tl), "r"(s));
    asm("lop3.b32 %0, %1, 0x7fffffff, %2, 0x6A;" : "=r"(rh) : "r"(th), "r"(s));
    u64 r; asm("mov.b64 %0, {%1,%2};" : "=l"(r) : "r"(rl), "r"(rh));
    return r;
}

// ---------------------------------------------------------------------------
// Kernel 1: shared-staged GEMM  x^T @ [W1a | W1b], outputs PRESCALED by w/2,
// P/Q partials into g_PQp (b2 folded into gy==0).
// grid (N/128=4, 8 hu-chunks of 32, B), block 256. Thread: 2 n x 8 hu (f32x2).
// ---------------------------------------------------------------------------
__global__ void __launch_bounds__(256) precompute_AB(
        const float* __restrict__ x,
        const float* __restrict__ W1,
        const float* __restrict__ b1,
        const float* __restrict__ W2,
        const float* __restrict__ b2) {
    __shared__ float xs[C_ * 128];     // [c][n_loc]  32 KB
    __shared__ float ws[C_ * 32];      // [c][k]       8 KB
    __shared__ float w2s[32];
    __shared__ float b1s[32];
    __shared__ float sPart[4 * 128];   // [hgroup][n_loc] 2 KB

    const int tid = threadIdx.x;
    const int n0  = blockIdx.x * 128;
    const int gy  = blockIdx.y;        // 0..7
    const int b   = blockIdx.z;
    const bool isA = (gy < 4);
    const int h0   = (isA ? gy : gy - 4) * 32;   // output h base 0..96
    const int crow = isA ? 0 : C_;               // W1 row offset

    // Stage x tile: 64c x 128n = 2048 float4, 8 per thread.
    const float* xb = x + (size_t)(b * C_) * N_ + n0;
    #pragma unroll
    for (int r = 0; r < 8; r++) {
        int idx = tid + 256 * r;
        int c   = idx >> 5;
        int n4  = idx & 31;
        ((float4*)(xs + c * 128))[n4] = ((const float4*)(xb + (size_t)c * N_))[n4];
    }
    // Stage W slice: 64c x 32hu = 512 float4, 2 per thread.
    #pragma unroll
    for (int r = 0; r < 2; r++) {
        int idx = tid + 256 * r;
        int c   = idx >> 3;
        int k4  = idx & 7;
        ((float4*)(ws + c * 32))[k4] =
            ((const float4*)(W1 + (size_t)(crow + c) * H_ + h0))[k4];
    }
    if (tid < 32) {
        w2s[tid] = 0.5f * W2[h0 + tid];        // signed w/2
        b1s[tid] = isA ? b1[h0 + tid] : 0.0f;
    }
    __syncthreads();

    const int nl0 = (tid & 63) * 2;
    const int hl0 = (tid >> 6) * 8;

    u64 acc[2][4];
    #pragma unroll
    for (int p = 0; p < 2; p++)
        #pragma unroll
        for (int k = 0; k < 4; k++) acc[p][k] = 0ULL;

    #pragma unroll 8
    for (int c = 0; c < C_; c++) {
        float2 xv = *(const float2*)(xs + c * 128 + nl0);
        u64 x0 = dup32(xv.x);
        u64 x1 = dup32(xv.y);
        const ulonglong2* wp = (const ulonglong2*)(ws + c * 32 + hl0);
        ulonglong2 w01 = wp[0];
        ulonglong2 w23 = wp[1];
        acc[0][0] = f32x2_fma(x0, w01.x, acc[0][0]);
        acc[0][1] = f32x2_fma(x0, w01.y, acc[0][1]);
        acc[0][2] = f32x2_fma(x0, w23.x, acc[0][2]);
        acc[0][3] = f32x2_fma(x0, w23.y, acc[0][3]);
        acc[1][0] = f32x2_fma(x1, w01.x, acc[1][0]);
        acc[1][1] = f32x2_fma(x1, w01.y, acc[1][1]);
        acc[1][2] = f32x2_fma(x1, w23.x, acc[1][2]);
        acc[1][3] = f32x2_fma(x1, w23.y, acc[1][3]);
    }

    // Epilogue: add b1, SCALE by w/2, store float2, accumulate P/Q partials.
    float* outb = (isA ? g_A : g_Bv) + (size_t)(b * H_ + h0) * N_ + n0 + nl0;
    float p0 = 0.f, p1 = 0.f;
    #pragma unroll
    for (int k = 0; k < 4; k++) {
        #pragma unroll
        for (int s = 0; s < 2; s++) {
            int hl = hl0 + 2 * k + s;
            float bias = b1s[hl];
            float w    = w2s[hl];
            float a0 = ((s ? hi32(acc[0][k]) : lo32(acc[0][k])) + bias) * w;
            float a1 = ((s ? hi32(acc[1][k]) : lo32(acc[1][k])) + bias) * w;
            *(float2*)(outb + (size_t)hl * N_) = make_float2(a0, a1);
            p0 += a0;
            p1 += a1;
        }
    }
    sPart[(tid >> 6) * 128 + nl0]     = p0;
    sPart[(tid >> 6) * 128 + nl0 + 1] = p1;
    __syncthreads();
    if (tid < 128) {
        float s = sPart[tid] + sPart[128 + tid] + sPart[256 + tid] + sPart[384 + tid];
        if (gy == 0) s += b2[0];
        g_PQp[gy * (B_ * N_) + b * N_ + n0 + tid] = s;
    }
}

// ---------------------------------------------------------------------------
// Kernel 2: grid 256 (1D), 512 threads.
//   bid < 144: compute 64x64 tile t=bid>>2, b=bid&3 (upper-tri):
//     y[i,j] = P_i + Q_j + sum_h sign(w_h)|A_ih + B_jh|   (A,B prescaled by w/2)
//   bid >= 144: zero-fill strict-lower 64x64 tiles.
// Thread: 2i x 4j packed f32x2: ADD2 -> LOP3(abs^sign) -> ADD2. No multiplies.
// A duplicated in smem, rows 128 floats wide: dup'd element ii at 2*ii.
// ---------------------------------------------------------------------------
__global__ void __launch_bounds__(512) pairwise_score(
        const float* __restrict__ W2,
        float* __restrict__ out) {
    const int t   = blockIdx.x;
    const int tid = threadIdx.x;

    if (t >= 144) {   // zero-fill strict-lower tiles
        int z  = t - 144;
        int b  = z & 3;
        int zt = z >> 2;              // 0..27
        float* outb = out + (size_t)b * N_ * N_
                    + (size_t)(c_LI[zt] * 64) * N_ + c_LJ[zt] * 64;
        const float4 zf = make_float4(0.f, 0.f, 0.f, 0.f);
        #pragma unroll
        for (int r = 0; r < 2; r++) {
            int l  = tid + 512 * r;   // float4 index 0..1023
            int ii = l >> 4;
            int j4 = l & 15;
            ((float4*)(outb + (size_t)ii * N_))[j4] = zf;
        }
        return;
    }

    const int b  = t & 3;
    const int tl = t >> 2;            // 0..35
    const int It = c_IT[tl];
    const int Jt = c_JT[tl];
    float* outb = out + (size_t)b * N_ * N_;

    __shared__ __align__(16) float Adup[64 * 128]; // [hh][2*ii] dup'd, 32 KB
    __shared__ __align__(16) float Bsh [64 * 64];  // [hh][jj],         16 KB
    __shared__ unsigned Ssh[H_];                   // signbit(w_h)
    __shared__ float Psh[64];                      // includes b2
    __shared__ float Qsh[64];

    // One-time staging of sign masks and P/Q.
    if (tid < H_) {
        Ssh[tid] = __float_as_uint(W2[tid]) & 0x80000000u;
    } else if (tid < 192) {
        int k = tid - 128;            // 0..63
        int n = It * 64 + k;
        Psh[k] = g_PQp[0 * B_ * N_ + b * N_ + n] + g_PQp[1 * B_ * N_ + b * N_ + n]
               + g_PQp[2 * B_ * N_ + b * N_ + n] + g_PQp[3 * B_ * N_ + b * N_ + n];
    } else if (tid < 256) {
        int k = tid - 192;            // 0..63
        int n = Jt * 64 + k;
        Qsh[k] = g_PQp[4 * B_ * N_ + b * N_ + n] + g_PQp[5 * B_ * N_ + b * N_ + n]
               + g_PQp[6 * B_ * N_ + b * N_ + n] + g_PQp[7 * B_ * N_ + b * N_ + n];
    }

    const int il0 = (tid >> 4) * 2;   // 0..62 (i-local base, 2 rows per thread)
    const int jl0 = (tid & 15) * 4;   // 0..60

    u64 acc00 = 0, acc01 = 0, acc10 = 0, acc11 = 0;  // [p][q-pair]

    #pragma unroll
    for (int hb = 0; hb < 2; hb++) {
        if (hb) __syncthreads();      // protect restaging against prior reads
        const float* Ag = g_A  + (size_t)(b * H_ + hb * 64) * N_ + It * 64;
        const float* Bg = g_Bv + (size_t)(b * H_ + hb * 64) * N_ + Jt * 64;
        // Stage A duplicated into 128-wide rows: 64hh x 16 src float4 = 1024
        // tasks, 2 per thread. Element ii=4*c4+k lands at row offset 2*ii.
        #pragma unroll
        for (int r = 0; r < 2; r++) {
            int l  = tid + 512 * r;   // 0..1023
            int hh = l >> 4;          // 0..63
            int c4 = l & 15;          // 0..15
            float4 v = ((const float4*)(Ag + (size_t)hh * N_))[c4];
            float* d = Adup + hh * 128 + c4 * 8;
            ((float4*)d)[0] = make_float4(v.x, v.x, v.y, v.y);
            ((float4*)d)[1] = make_float4(v.z, v.z, v.w, v.w);
        }
        // Stage B natural: 64hh x 16 float4 = 1024, 2 per thread.
        #pragma unroll
        for (int r = 0; r < 2; r++) {
            int l  = tid + 512 * r;
            int hh = l >> 4;
            int c4 = l & 15;
            ((float4*)(Bsh + hh * 64))[c4] = ((const float4*)(Bg + (size_t)hh * N_))[c4];
        }
        __syncthreads();

        const float*    Ap = Adup + il0 * 2;   // dup pair of (a_il0, a_il0+1)
        const float*    Bp = Bsh + jl0;
        const unsigned* Sp = Ssh + hb * 64;
        #pragma unroll 8
        for (int hh = 0; hh < 64; hh++) {
            unsigned s = Sp[hh];
            ulonglong2 ad = *(const ulonglong2*)(Ap + hh * 128); // dup(a0), dup(a1)
            ulonglong2 bb = *(const ulonglong2*)(Bp + hh * 64);  // (b0,b1),(b2,b3)
            acc00 = f32x2_add(acc00, absxor2(f32x2_add(ad.x, bb.x), s));
            acc01 = f32x2_add(acc01, absxor2(f32x2_add(ad.x, bb.y), s));
            acc10 = f32x2_add(acc10, absxor2(f32x2_add(ad.y, bb.x), s));
            acc11 = f32x2_add(acc11, absxor2(f32x2_add(ad.y, bb.y), s));
        }
    }

    const int i0 = It * 64 + il0;
    const int j0 = Jt * 64 + jl0;
    const bool diag = (It == Jt);

    float p0 = Psh[il0], p1 = Psh[il0 + 1];
    float q0 = Qsh[jl0], q1 = Qsh[jl0 + 1], q2 = Qsh[jl0 + 2], q3 = Qsh[jl0 + 3];

    // acc00 = row i0 (j0,j0+1); acc01 = row i0 (j0+2,j0+3); acc1x = row i0+1.
    float4 v0, v1;
    v0.x = p0 + q0 + lo32(acc00); v0.y = p0 + q1 + hi32(acc00);
    v0.z = p0 + q2 + lo32(acc01); v0.w = p0 + q3 + hi32(acc01);
    v1.x = p1 + q0 + lo32(acc10); v1.y = p1 + q1 + hi32(acc10);
    v1.z = p1 + q2 + lo32(acc11); v1.w = p1 + q3 + hi32(acc11);

    if (diag) {   // strict upper-triangle mask j > i
        if (!(j0 + 0 > i0)) v0.x = 0.f;
        if (!(j0 + 1 > i0)) v0.y = 0.f;
        if (!(j0 + 2 > i0)) v0.z = 0.f;
        if (!(j0 + 3 > i0)) v0.w = 0.f;
        int i1 = i0 + 1;
        if (!(j0 + 0 > i1)) v1.x = 0.f;
        if (!(j0 + 1 > i1)) v1.y = 0.f;
        if (!(j0 + 2 > i1)) v1.z = 0.f;
        if (!(j0 + 3 > i1)) v1.w = 0.f;
    }
    *(float4*)(outb + (size_t)i0 * N_ + j0)       = v0;
    *(float4*)(outb + (size_t)(i0 + 1) * N_ + j0) = v1;
}

// ---------------------------------------------------------------------------
// Inputs: 0:x (B,C,N) f32, 1:W1 (2C,H) f32, 2:b1 (H) f32, 3:W2 (H,1) f32,
//         4:b2 (1) f32.  Output: (B,N,N) f32.
// ---------------------------------------------------------------------------
extern "C" void kernel_launch(void* const* d_in, const int* in_sizes, int n_in,
                              void* d_out, int out_size) {
    const float* x  = (const float*)d_in[0];
    const float* W1 = (const float*)d_in[1];
    const float* b1 = (const float*)d_in[2];
    const float* W2 = (const float*)d_in[3];
    const float* b2 = (const float*)d_in[4];
    float* out = (float*)d_out;

    dim3 g1(N_ / 128, 8, B_);     // (4, 8, 4) = 128 blocks
    precompute_AB<<<g1, 256>>>(x, W1, b1, W2, b2);

    pairwise_score<<<256, 512>>>(W2, out);   // 144 compute + 112 zero-fill
}

// round 12
// speedup vs baseline: 1.3607x; 1.2056x over previous
#include <cuda_runtime.h>

// Problem constants: B=4, C=64, N=512, H=128, 2C=128.
#define B_ 4
#define C_ 64
#define N_ 512
#define H_ 128

typedef unsigned long long u64;

// Scratch (h-major, plain f32):
//   g_A [b][h][n] = b1[h] + sum_c x[b,c,n]*W1[c][h]
//   g_Bv[b][h][n] =         sum_c x[b,c,n]*W1[C+c][h]
//   g_PQp[gy][b][n]: gy 0..3 = P partials (32-h chunks), gy 4..7 = Q partials,
//   with P = sum_h (W2[h]/2)*A, Q = sum_h (W2[h]/2)*Bv.
__device__ float g_A  [B_ * H_ * N_];
__device__ float g_Bv [B_ * H_ * N_];
__device__ float g_PQp[8 * B_ * N_];

// Upper-triangle (It<=Jt, 36) and strict-lower (It>Jt, 28) 64x64 tile lists.
__constant__ signed char c_IT[36] = {0,0,0,0,0,0,0,0, 1,1,1,1,1,1,1, 2,2,2,2,2,2,
                                     3,3,3,3,3, 4,4,4,4, 5,5,5, 6,6, 7};
__constant__ signed char c_JT[36] = {0,1,2,3,4,5,6,7, 1,2,3,4,5,6,7, 2,3,4,5,6,7,
                                     3,4,5,6,7, 4,5,6,7, 5,6,7, 6,7, 7};
__constant__ signed char c_LI[28] = {1, 2,2, 3,3,3, 4,4,4,4, 5,5,5,5,5,
                                     6,6,6,6,6,6, 7,7,7,7,7,7,7};
__constant__ signed char c_LJ[28] = {0, 0,1, 0,1,2, 0,1,2,3, 0,1,2,3,4,
                                     0,1,2,3,4,5, 0,1,2,3,4,5,6};

// ---- packed f32x2 helpers (used only in kernel 1) --------------------------
__device__ __forceinline__ u64 f32x2_fma(u64 a, u64 b, u64 c) {
    u64 r; asm("fma.rn.f32x2 %0, %1, %2, %3;" : "=l"(r) : "l"(a), "l"(b), "l"(c)); return r;
}
__device__ __forceinline__ u64 dup32(float x) {
    u64 r; asm("mov.b64 %0, {%1, %1};" : "=l"(r) : "f"(x)); return r;
}
__device__ __forceinline__ float lo32(u64 v) { return __uint_as_float((unsigned)v); }
__device__ __forceinline__ float hi32(u64 v) { return __uint_as_float((unsigned)(v >> 32)); }

// ---------------------------------------------------------------------------
// Kernel 1: shared-staged GEMM  x^T @ [W1a | W1b] -> g_A (b1 folded), g_Bv,
// plus per-chunk P/Q partials into g_PQp.
// grid (N/128=4, 8 hu-chunks of 32, B), block 256. Thread: 2 n x 8 hu (f32x2).
// ---------------------------------------------------------------------------
__global__ void __launch_bounds__(256) precompute_AB(
        const float* __restrict__ x,
        const float* __restrict__ W1,
        const float* __restrict__ b1,
        const float* __restrict__ W2) {
    __shared__ float xs[C_ * 128];     // [c][n_loc]  32 KB
    __shared__ float ws[C_ * 32];      // [c][k]       8 KB
    __shared__ float w2s[32];
    __shared__ float b1s[32];
    __shared__ float sPart[4 * 128];   // [hgroup][n_loc] 2 KB

    const int tid = threadIdx.x;
    const int n0  = blockIdx.x * 128;
    const int gy  = blockIdx.y;        // 0..7
    const int b   = blockIdx.z;
    const bool isA = (gy < 4);
    const int h0   = (isA ? gy : gy - 4) * 32;   // output h base 0..96
    const int crow = isA ? 0 : C_;               // W1 row offset

    // Stage x tile: 64c x 128n = 2048 float4, 8 per thread.
    const float* xb = x + (size_t)(b * C_) * N_ + n0;
    #pragma unroll
    for (int r = 0; r < 8; r++) {
        int idx = tid + 256 * r;
        int c   = idx >> 5;
        int n4  = idx & 31;
        ((float4*)(xs + c * 128))[n4] = ((const float4*)(xb + (size_t)c * N_))[n4];
    }
    // Stage W slice: 64c x 32hu = 512 float4, 2 per thread.
    #pragma unroll
    for (int r = 0; r < 2; r++) {
        int idx = tid + 256 * r;
        int c   = idx >> 3;
        int k4  = idx & 7;
        ((float4*)(ws + c * 32))[k4] =
            ((const float4*)(W1 + (size_t)(crow + c) * H_ + h0))[k4];
    }
    if (tid < 32) {
        w2s[tid] = 0.5f * W2[h0 + tid];
        b1s[tid] = isA ? b1[h0 + tid] : 0.0f;
    }
    __syncthreads();

    const int nl0 = (tid & 63) * 2;
    const int hl0 = (tid >> 6) * 8;

    u64 acc[2][4];
    #pragma unroll
    for (int p = 0; p < 2; p++)
        #pragma unroll
        for (int k = 0; k < 4; k++) acc[p][k] = 0ULL;

    #pragma unroll 8
    for (int c = 0; c < C_; c++) {
        float2 xv = *(const float2*)(xs + c * 128 + nl0);
        u64 x0 = dup32(xv.x);
        u64 x1 = dup32(xv.y);
        const ulonglong2* wp = (const ulonglong2*)(ws + c * 32 + hl0);
        ulonglong2 w01 = wp[0];
        ulonglong2 w23 = wp[1];
        acc[0][0] = f32x2_fma(x0, w01.x, acc[0][0]);
        acc[0][1] = f32x2_fma(x0, w01.y, acc[0][1]);
        acc[0][2] = f32x2_fma(x0, w23.x, acc[0][2]);
        acc[0][3] = f32x2_fma(x0, w23.y, acc[0][3]);
        acc[1][0] = f32x2_fma(x1, w01.x, acc[1][0]);
        acc[1][1] = f32x2_fma(x1, w01.y, acc[1][1]);
        acc[1][2] = f32x2_fma(x1, w23.x, acc[1][2]);
        acc[1][3] = f32x2_fma(x1, w23.y, acc[1][3]);
    }

    // Epilogue: add b1, store float2 (n, n+1) per h, accumulate P/Q partials.
    float* outb = (isA ? g_A : g_Bv) + (size_t)(b * H_ + h0) * N_ + n0 + nl0;
    float p0 = 0.f, p1 = 0.f;
    #pragma unroll
    for (int k = 0; k < 4; k++) {
        #pragma unroll
        for (int s = 0; s < 2; s++) {
            int hl = hl0 + 2 * k + s;
            float bias = b1s[hl];
            float a0 = (s ? hi32(acc[0][k]) : lo32(acc[0][k])) + bias;
            float a1 = (s ? hi32(acc[1][k]) : lo32(acc[1][k])) + bias;
            *(float2*)(outb + (size_t)hl * N_) = make_float2(a0, a1);
            float w = w2s[hl];
            p0 = fmaf(w, a0, p0);
            p1 = fmaf(w, a1, p1);
        }
    }
    sPart[(tid >> 6) * 128 + nl0]     = p0;
    sPart[(tid >> 6) * 128 + nl0 + 1] = p1;
    __syncthreads();
    if (tid < 128) {
        float s = sPart[tid] + sPart[128 + tid] + sPart[256 + tid] + sPart[384 + tid];
        g_PQp[gy * (B_ * N_) + b * N_ + n0 + tid] = s;
    }
}

// ---------------------------------------------------------------------------
// Kernel 2: grid 256 (1D), 256 threads.
//   bid < 144: compute 64x64 tile t=bid>>2, b=bid&3 (upper-tri):
//     y[i,j] = P_i + b2 + Q_j + sum_h w'_h |A_ih + B_jh|
//   bid >= 144: zero-fill strict-lower 64x64 tiles.
// Thread: 4i x 4j scalar (FADD + FFMA with |src| modifier), SOFTWARE-PIPELINED:
// hh+1's A/B are prefetched into registers before hh's 32 FMAs; w loaded as
// float4 per 4 hh. Smem rows padded to 65 so the last prefetch stays in-bounds.
// ---------------------------------------------------------------------------
__global__ void __launch_bounds__(256) pairwise_score(
        const float* __restrict__ W2,
        const float* __restrict__ b2,
        float* __restrict__ out) {
    const int t   = blockIdx.x;
    const int tid = threadIdx.x;

    if (t >= 144) {   // zero-fill strict-lower tiles
        int z  = t - 144;
        int b  = z & 3;
        int zt = z >> 2;              // 0..27
        float* outb = out + (size_t)b * N_ * N_
                    + (size_t)(c_LI[zt] * 64) * N_ + c_LJ[zt] * 64;
        const float4 zf = make_float4(0.f, 0.f, 0.f, 0.f);
        #pragma unroll
        for (int r = 0; r < 4; r++) {
            int l  = tid + 256 * r;   // float4 index 0..1023
            int ii = l >> 4;
            int j4 = l & 15;
            ((float4*)(outb + (size_t)ii * N_))[j4] = zf;
        }
        return;
    }

    const int b  = t & 3;
    const int tl = t >> 2;            // 0..35
    const int It = c_IT[tl];
    const int Jt = c_JT[tl];
    float* outb = out + (size_t)b * N_ * N_;

    __shared__ __align__(16) float Ash[65 * 64];  // [hh][ii], 1 pad row
    __shared__ __align__(16) float Bsh[65 * 64];  // [hh][jj], 1 pad row
    __shared__ float Wsh[H_];         // w/2
    __shared__ float Psh[64];         // includes b2
    __shared__ float Qsh[64];

    if (tid < H_) {
        Wsh[tid] = 0.5f * W2[tid];
    } else if (tid < 192) {
        int k = tid - 128;            // 0..63
        int n = It * 64 + k;
        Psh[k] = g_PQp[0 * B_ * N_ + b * N_ + n] + g_PQp[1 * B_ * N_ + b * N_ + n]
               + g_PQp[2 * B_ * N_ + b * N_ + n] + g_PQp[3 * B_ * N_ + b * N_ + n]
               + b2[0];
    } else {
        int k = tid - 192;            // 0..63
        int n = Jt * 64 + k;
        Qsh[k] = g_PQp[4 * B_ * N_ + b * N_ + n] + g_PQp[5 * B_ * N_ + b * N_ + n]
               + g_PQp[6 * B_ * N_ + b * N_ + n] + g_PQp[7 * B_ * N_ + b * N_ + n];
    }

    const int il0 = (tid >> 4) * 4;   // 0..60
    const int jl0 = (tid & 15) * 4;   // 0..60

    float acc[4][4];
    #pragma unroll
    for (int p = 0; p < 4; p++)
        #pragma unroll
        for (int q = 0; q < 4; q++) acc[p][q] = 0.0f;

    #pragma unroll
    for (int hb = 0; hb < 2; hb++) {
        __syncthreads();
        const float* Ag = g_A  + (size_t)(b * H_ + hb * 64) * N_ + It * 64;
        const float* Bg = g_Bv + (size_t)(b * H_ + hb * 64) * N_ + Jt * 64;
        // Stage A and B: 64hh x 64 each = 1024 float4 apiece, 4 per thread.
        #pragma unroll
        for (int r = 0; r < 4; r++) {
            int l  = tid + 256 * r;   // float4 index 0..1023
            int hh = l >> 4;
            int c4 = l & 15;
            ((float4*)(Ash + hh * 64))[c4] = ((const float4*)(Ag + (size_t)hh * N_))[c4];
            ((float4*)(Bsh + hh * 64))[c4] = ((const float4*)(Bg + (size_t)hh * N_))[c4];
        }
        __syncthreads();

        const float* Ap = Ash + il0;
        const float* Bp = Bsh + jl0;
        const float* Wp = Wsh + hb * 64;

        // Software-pipelined main loop: prefetch hh+1 before hh's 32 FMAs.
        float4 av = *(const float4*)Ap;
        float4 bv = *(const float4*)Bp;
        #pragma unroll 2
        for (int h4 = 0; h4 < 16; h4++) {
            float4 wv = *(const float4*)(Wp + h4 * 4);
            #pragma unroll
            for (int k = 0; k < 4; k++) {
                int hh = h4 * 4 + k;
                float4 an = *(const float4*)(Ap + (hh + 1) * 64);  // pad row @64
                float4 bn = *(const float4*)(Bp + (hh + 1) * 64);
                float w = (k == 0) ? wv.x : (k == 1) ? wv.y : (k == 2) ? wv.z : wv.w;
                float a_[4] = {av.x, av.y, av.z, av.w};
                float b_[4] = {bv.x, bv.y, bv.z, bv.w};
                #pragma unroll
                for (int p = 0; p < 4; p++)
                    #pragma unroll
                    for (int q = 0; q < 4; q++)
                        acc[p][q] = fmaf(fabsf(a_[p] + b_[q]), w, acc[p][q]);
                av = an;
                bv = bn;
            }
        }
    }

    const int i0 = It * 64 + il0;
    const int j0 = Jt * 64 + jl0;
    const bool diag = (It == Jt);

    float q0 = Qsh[jl0], q1 = Qsh[jl0 + 1], q2 = Qsh[jl0 + 2], q3 = Qsh[jl0 + 3];
    #pragma unroll
    for (int p = 0; p < 4; p++) {
        int i = i0 + p;
        float pb = Psh[il0 + p];
        float4 v;
        v.x = pb + q0 + acc[p][0];
        v.y = pb + q1 + acc[p][1];
        v.z = pb + q2 + acc[p][2];
        v.w = pb + q3 + acc[p][3];
        if (diag) {   // strict upper-triangle mask j > i
            if (!(j0 + 0 > i)) v.x = 0.f;
            if (!(j0 + 1 > i)) v.y = 0.f;
            if (!(j0 + 2 > i)) v.z = 0.f;
            if (!(j0 + 3 > i)) v.w = 0.f;
        }
        *(float4*)(outb + (size_t)i * N_ + j0) = v;
    }
}

// ---------------------------------------------------------------------------
// Inputs: 0:x (B,C,N) f32, 1:W1 (2C,H) f32, 2:b1 (H) f32, 3:W2 (H,1) f32,
//         4:b2 (1) f32.  Output: (B,N,N) f32.
// ---------------------------------------------------------------------------
extern "C" void kernel_launch(void* const* d_in, const int* in_sizes, int n_in,
                              void* d_out, int out_size) {
    const float* x  = (const float*)d_in[0];
    const float* W1 = (const float*)d_in[1];
    const float* b1 = (const float*)d_in[2];
    const float* W2 = (const float*)d_in[3];
    const float* b2 = (const float*)d_in[4];
    float* out = (float*)d_out;

    dim3 g1(N_ / 128, 8, B_);     // (4, 8, 4) = 128 blocks
    precompute_AB<<<g1, 256>>>(x, W1, b1, W2);

    pairwise_score<<<256, 256>>>(W2, b2, out);   // 144 compute + 112 zero-fill
}